// round 16
// baseline (speedup 1.0000x reference)
#include <cuda_runtime.h>
#include <cuda_bf16.h>

// ---------------- device scratch (no allocs allowed) ----------------
__device__ float g_q[8192*256];   // (b*t, h*64+d), q pre-scaled by 1/8
__device__ float g_k[8192*256];
__device__ float g_v[8192*256];
__device__ float g_o[8192*256];   // attention output (pre-Wo), merged heads
__device__ float g_Wc[16*256];    // combined gate weights
__device__ float g_bc[16];        // combined gate bias (+theta)
__device__ float g_A[512*16*16];  // (t, b, gate*4+w) precomputed angles
__device__ float g_hs[512*16*4];  // lstm hidden states (t, b, w)
// split-precision bf16 operands, row-major:
// A' = [Ahi | Alo | Ahi] along K' (768): [8192][768]
__device__ __align__(16) unsigned short g_Abf[8192*768];
// B' = [Whi | Whi | Wlo]: rows = output col n (768 = q|k|v), cols = K' (768)
__device__ __align__(16) unsigned short g_Bbf[768*768];

__device__ __forceinline__ float tanh_fast(float x) {
    float y; asm("tanh.approx.f32 %0, %1;" : "=f"(y) : "f"(x)); return y;
}
__device__ __forceinline__ unsigned smem_u32(const void* p) {
    unsigned a; asm("{ .reg .u64 t; cvta.to.shared.u64 t, %1; cvt.u32.u64 %0, t; }" : "=r"(a) : "l"(p));
    return a;
}
__device__ __forceinline__ void ldm4(unsigned& r0, unsigned& r1, unsigned& r2, unsigned& r3, unsigned addr) {
    asm volatile("ldmatrix.sync.aligned.m8n8.x4.shared.b16 {%0,%1,%2,%3}, [%4];"
                 : "=r"(r0), "=r"(r1), "=r"(r2), "=r"(r3) : "r"(addr));
}
__device__ __forceinline__ void mma16816(float* c, const unsigned* a, const unsigned* b) {
    asm volatile("mma.sync.aligned.m16n8k16.row.col.f32.bf16.bf16.f32 "
                 "{%0,%1,%2,%3}, {%4,%5,%6,%7}, {%8,%9}, {%0,%1,%2,%3};"
                 : "+f"(c[0]), "+f"(c[1]), "+f"(c[2]), "+f"(c[3])
                 : "r"(a[0]), "r"(a[1]), "r"(a[2]), "r"(a[3]), "r"(b[0]), "r"(b[1]));
}

#define FS 68   // padded stride (68 floats = 272B, 16B-aligned rows)

// =====================================================================
// P1: gather emb rows, split fp32 -> bf16 hi/lo, write row-major A'.
// =====================================================================
__global__ void k_prepA(const int* __restrict__ sent, const float* __restrict__ emb)
{
    const int idx = blockIdx.x * 256 + threadIdx.x;   // 8192*128
    const int r = idx >> 7, c = (idx & 127) * 2;
    const float2 x = *(const float2*)(emb + (size_t)sent[r] * 256 + c);
    const __nv_bfloat16 h0 = __float2bfloat16(x.x), h1 = __float2bfloat16(x.y);
    const __nv_bfloat16 l0 = __float2bfloat16(x.x - __bfloat162float(h0));
    const __nv_bfloat16 l1 = __float2bfloat16(x.y - __bfloat162float(h1));
    const unsigned hp = (unsigned)__bfloat16_as_ushort(h0) | ((unsigned)__bfloat16_as_ushort(h1) << 16);
    const unsigned lp = (unsigned)__bfloat16_as_ushort(l0) | ((unsigned)__bfloat16_as_ushort(l1) << 16);
    unsigned short* dst = g_Abf + (size_t)r * 768;
    *(unsigned*)(dst + c)       = hp;
    *(unsigned*)(dst + 256 + c) = lp;
    *(unsigned*)(dst + 512 + c) = hp;
}

// =====================================================================
// P2: same for stacked weights [Wq;Wk;Wv] (768 x 256) -> B'.
// =====================================================================
__global__ void k_prepB(const float* __restrict__ Wq, const float* __restrict__ Wk,
                        const float* __restrict__ Wv)
{
    const int idx = blockIdx.x * 256 + threadIdx.x;   // 768*128
    const int n = idx >> 7, c = (idx & 127) * 2;
    const int which = n >> 8, wn = n & 255;
    const float* W = (which == 0) ? Wq : (which == 1) ? Wk : Wv;
    const float2 x = *(const float2*)(W + (size_t)wn * 256 + c);
    const __nv_bfloat16 h0 = __float2bfloat16(x.x), h1 = __float2bfloat16(x.y);
    const __nv_bfloat16 l0 = __float2bfloat16(x.x - __bfloat162float(h0));
    const __nv_bfloat16 l1 = __float2bfloat16(x.y - __bfloat162float(h1));
    const unsigned hp = (unsigned)__bfloat16_as_ushort(h0) | ((unsigned)__bfloat16_as_ushort(h1) << 16);
    const unsigned lp = (unsigned)__bfloat16_as_ushort(l0) | ((unsigned)__bfloat16_as_ushort(l1) << 16);
    unsigned short* dst = g_Bbf + (size_t)n * 768;
    *(unsigned*)(dst + c)       = hp;   // pairs Ahi
    *(unsigned*)(dst + 256 + c) = hp;   // pairs Alo
    *(unsigned*)(dst + 512 + c) = lp;   // pairs Ahi
}

// =====================================================================
// K1: QKV GEMM on tensor cores via mma.sync (m16n8k16 bf16, f32 acc).
// grid (64 mt, 6 nt), 256 thr = 8 warps (4m x 2n), warp tile 32x64.
// C[128x128] = A'[128x768] * B'[128x768]^T.
// =====================================================================
__global__ void __launch_bounds__(256, 2) k_qkv_mma(
    const float* __restrict__ bq, const float* __restrict__ bk, const float* __restrict__ bv)
{
    __shared__ __align__(16) unsigned short As[128][72];
    __shared__ __align__(16) unsigned short Bs[128][72];
    const int tid = threadIdx.x;
    const int warp = tid >> 5, lane = tid & 31;
    const int wm = warp >> 1, wn = warp & 1;
    const int mt = blockIdx.x, nt = blockIdx.y;

    float c[2][8][4] = {};

    for (int kc = 0; kc < 12; ++kc) {
        // load A[128x64], B[128x64] bf16 chunks (uint4 = 8 bf16 each)
#pragma unroll
        for (int i = 0; i < 4; ++i) {
            const int e = tid + i * 256;          // 0..1023
            const int row = e >> 3, c16 = e & 7;
            *(uint4*)&As[row][c16 * 8] =
                *(const uint4*)(g_Abf + (size_t)(mt * 128 + row) * 768 + kc * 64 + c16 * 8);
            *(uint4*)&Bs[row][c16 * 8] =
                *(const uint4*)(g_Bbf + (size_t)(nt * 128 + row) * 768 + kc * 64 + c16 * 8);
        }
        __syncthreads();

#pragma unroll
        for (int ks = 0; ks < 4; ++ks) {
            unsigned a[2][4];
#pragma unroll
            for (int mi = 0; mi < 2; ++mi) {
                const unsigned addr = smem_u32(&As[wm * 32 + mi * 16 + (lane & 15)][ks * 16 + (lane >> 4) * 8]);
                ldm4(a[mi][0], a[mi][1], a[mi][2], a[mi][3], addr);
            }
            unsigned b[8][2];
#pragma unroll
            for (int nb4 = 0; nb4 < 4; ++nb4) {
                unsigned r0, r1, r2, r3;
                const unsigned addr = smem_u32(&Bs[wn * 64 + nb4 * 16 + (lane & 15)][ks * 16 + (lane >> 4) * 8]);
                ldm4(r0, r1, r2, r3, addr);
                b[nb4 * 2][0] = r0; b[nb4 * 2 + 1][0] = r1;
                b[nb4 * 2][1] = r2; b[nb4 * 2 + 1][1] = r3;
            }
#pragma unroll
            for (int mi = 0; mi < 2; ++mi)
#pragma unroll
                for (int nb = 0; nb < 8; ++nb)
                    mma16816(c[mi][nb], a[mi], b[nb]);
        }
        __syncthreads();
    }

    // epilogue: bias + q-scale, direct float2 stores
    const int ncol0 = nt << 7;
    const int which = ncol0 >> 8, wn0 = ncol0 & 255;
    const float* bias = (which == 0) ? bq : (which == 1) ? bk : bv;
    const float qs = (which == 0) ? 0.125f : 1.0f;
    float* dst = (which == 0) ? g_q : (which == 1) ? g_k : g_v;
#pragma unroll
    for (int mi = 0; mi < 2; ++mi) {
        const int row = mt * 128 + wm * 32 + mi * 16 + (lane >> 2);
#pragma unroll
        for (int nb = 0; nb < 8; ++nb) {
            const int colg = wn0 + wn * 64 + nb * 8 + (lane & 3) * 2;
            const float b0 = bias[colg], b1 = bias[colg + 1];
            *(float2*)(dst + (size_t)row * 256 + colg) =
                make_float2((c[mi][nb][0] + b0) * qs, (c[mi][nb][1] + b1) * qs);
            *(float2*)(dst + (size_t)(row + 8) * 256 + colg) =
                make_float2((c[mi][nb][2] + b0) * qs, (c[mi][nb][3] + b1) * qs);
        }
    }
}

// =====================================================================
// K2: flash attention, no-max softmax, SIMT.
// =====================================================================
__global__ void __launch_bounds__(256, 3) k_flash()
{
    extern __shared__ __align__(16) float sm[];
    float (*QT)[FS] = (float(*)[FS])sm;
    float (*KP)[FS] = (float(*)[FS])(sm + 64 * FS);
    float (*Vs)[64] = (float(*)[64])(sm + 2 * 64 * FS);

    const int bh = blockIdx.y;
    const int b = bh >> 2, h = bh & 3;
    const int m0 = blockIdx.x * 64;
    const int tid = threadIdx.x;
    const int ty = tid >> 4, tx = tid & 15;
    const float* Q = g_q + ((size_t)(b * 512 + m0)) * 256 + h * 64;
    const float* K = g_k + ((size_t)(b * 512)) * 256 + h * 64;
    const float* V = g_v + ((size_t)(b * 512)) * 256 + h * 64;

    {
        const int lm = tid >> 2, lk = (tid & 3) * 4;
#pragma unroll
        for (int c = 0; c < 64; c += 16) {
            float4 q4 = *(const float4*)(Q + (size_t)lm * 256 + lk + c);
            QT[lk + c + 0][lm] = q4.x; QT[lk + c + 1][lm] = q4.y;
            QT[lk + c + 2][lm] = q4.z; QT[lk + c + 3][lm] = q4.w;
        }
    }
    float o[4][4] = {};
    float lp[4] = {};

    for (int kk0 = 0; kk0 < 512; kk0 += 64) {
        {
            const int lm = tid >> 2, lk = (tid & 3) * 4;
#pragma unroll
            for (int c = 0; c < 64; c += 16) {
                float4 k4 = *(const float4*)(K + (size_t)(kk0 + lm) * 256 + lk + c);
                KP[lk + c + 0][lm] = k4.x; KP[lk + c + 1][lm] = k4.y;
                KP[lk + c + 2][lm] = k4.z; KP[lk + c + 3][lm] = k4.w;
            }
            const int vr = tid >> 4, vc = (tid & 15) * 4;
#pragma unroll
            for (int c = 0; c < 64; c += 16)
                *(float4*)&Vs[vr + c][vc] = *(const float4*)(V + (size_t)(kk0 + vr + c) * 256 + vc);
        }
        __syncthreads();

        float s[4][4] = {};
#pragma unroll
        for (int d = 0; d < 64; ++d) {
            float4 qv = *(const float4*)&QT[d][ty * 4];
            float4 kv = *(const float4*)&KP[d][tx * 4];
            float qr[4] = {qv.x, qv.y, qv.z, qv.w};
            float kr[4] = {kv.x, kv.y, kv.z, kv.w};
#pragma unroll
            for (int i = 0; i < 4; ++i)
#pragma unroll
                for (int j = 0; j < 4; ++j) s[i][j] += qr[i] * kr[j];
        }
#pragma unroll
        for (int i = 0; i < 4; ++i)
#pragma unroll
            for (int j = 0; j < 4; ++j) { s[i][j] = __expf(s[i][j]); lp[i] += s[i][j]; }
        __syncthreads();

#pragma unroll
        for (int i = 0; i < 4; ++i)
            *(float4*)&KP[ty * 4 + i][tx * 4] = make_float4(s[i][0], s[i][1], s[i][2], s[i][3]);
        __syncwarp();

#pragma unroll
        for (int k4 = 0; k4 < 16; ++k4) {
            float4 p0 = *(const float4*)&KP[ty * 4 + 0][k4 * 4];
            float4 p1 = *(const float4*)&KP[ty * 4 + 1][k4 * 4];
            float4 p2 = *(const float4*)&KP[ty * 4 + 2][k4 * 4];
            float4 p3 = *(const float4*)&KP[ty * 4 + 3][k4 * 4];
            float pr0[4] = {p0.x, p0.y, p0.z, p0.w};
            float pr1[4] = {p1.x, p1.y, p1.z, p1.w};
            float pr2[4] = {p2.x, p2.y, p2.z, p2.w};
            float pr3[4] = {p3.x, p3.y, p3.z, p3.w};
#pragma unroll
            for (int kk = 0; kk < 4; ++kk) {
                float4 vv = *(const float4*)&Vs[k4 * 4 + kk][tx * 4];
                o[0][0] += pr0[kk] * vv.x; o[0][1] += pr0[kk] * vv.y; o[0][2] += pr0[kk] * vv.z; o[0][3] += pr0[kk] * vv.w;
                o[1][0] += pr1[kk] * vv.x; o[1][1] += pr1[kk] * vv.y; o[1][2] += pr1[kk] * vv.z; o[1][3] += pr1[kk] * vv.w;
                o[2][0] += pr2[kk] * vv.x; o[2][1] += pr2[kk] * vv.y; o[2][2] += pr2[kk] * vv.z; o[2][3] += pr2[kk] * vv.w;
                o[3][0] += pr3[kk] * vv.x; o[3][1] += pr3[kk] * vv.y; o[3][2] += pr3[kk] * vv.z; o[3][3] += pr3[kk] * vv.w;
            }
        }
        __syncthreads();
    }

#pragma unroll
    for (int i = 0; i < 4; ++i) {
#pragma unroll
        for (int off = 8; off >= 1; off >>= 1)
            lp[i] += __shfl_xor_sync(0xffffffffu, lp[i], off, 16);
    }
#pragma unroll
    for (int i = 0; i < 4; ++i) {
        const float inv = __fdividef(1.f, lp[i]);
        float4 ov = make_float4(o[i][0] * inv, o[i][1] * inv, o[i][2] * inv, o[i][3] * inv);
        *(float4*)(g_o + (size_t)(b * 512 + m0 + ty * 4 + i) * 256 + h * 64 + tx * 4) = ov;
    }
}

// =====================================================================
// K3: fold Wo into gate projections — PARALLEL version (16 blocks).
// Block n computes Wc[n][0..255] and bc[n]. Wo column loads coalesced.
// =====================================================================
__global__ void k_combine(const float* __restrict__ Wf, const float* __restrict__ bf, const float* __restrict__ thf,
                          const float* __restrict__ Wi, const float* __restrict__ bi, const float* __restrict__ thi,
                          const float* __restrict__ Wg_, const float* __restrict__ bg, const float* __restrict__ thg,
                          const float* __restrict__ Wo2, const float* __restrict__ bo2, const float* __restrict__ tho,
                          const float* __restrict__ Wo, const float* __restrict__ bo)
{
    const int n = blockIdx.x;            // 0..15
    const int g = n >> 2, w = n & 3;
    const float* Wsel = (g == 0) ? Wf : (g == 1) ? Wi : (g == 2) ? Wg_ : Wo2;
    __shared__ float sw[256];
    __shared__ float red[256];
    const int c = threadIdx.x;
    sw[c] = Wsel[w * 260 + c];
    __syncthreads();

    float acc = 0.f;
#pragma unroll 4
    for (int d = 0; d < 256; ++d)
        acc += sw[d] * Wo[d * 256 + c];
    g_Wc[n * 256 + c] = acc;

    red[c] = sw[c] * bo[c];
    __syncthreads();
#pragma unroll
    for (int s = 128; s > 0; s >>= 1) {
        if (c < s) red[c] += red[c + s];
        __syncthreads();
    }
    if (c == 0) {
        const float bb = (g == 0) ? bf[w] : (g == 1) ? bi[w] : (g == 2) ? bg[w] : bo2[w];
        const float tt = (g == 0) ? thf[w] : (g == 1) ? thi[w] : (g == 2) ? thg[w] : tho[w];
        g_bc[n] = red[0] + bb + tt;
    }
}

// =====================================================================
// K4: gate angle precompute, rows staged through smem.
// =====================================================================
__global__ void k_gates()
{
    __shared__ float sW[256][16];
    __shared__ float sb[16];
    __shared__ __align__(16) float sX[16 * 256];
    const int tid = threadIdx.x;
    for (int e = tid; e < 4096; e += 256) {
        const int k = e >> 4, n = e & 15;
        sW[k][n] = g_Wc[n * 256 + k];
    }
    if (tid < 16) sb[tid] = g_bc[tid];
    const int r0 = blockIdx.x * 16;
    const float4* src = (const float4*)(g_o + (size_t)r0 * 256);
    float4* dst = (float4*)sX;
    for (int i = tid; i < 1024; i += 256) dst[i] = src[i];
    __syncthreads();

    const int n = tid & 15, lr = tid >> 4;
    const float* x = sX + lr * 256;
    float acc = 0.f;
#pragma unroll 8
    for (int k = 0; k < 256; k += 4) {
        float4 a4 = *(const float4*)(x + k);
        acc += a4.x * sW[k + 0][n] + a4.y * sW[k + 1][n] + a4.z * sW[k + 2][n] + a4.w * sW[k + 3][n];
    }
    const int r = r0 + lr, b = r >> 9, t = r & 511;
    g_A[(t * 16 + b) * 16 + n] = acc + sb[n];
}

// =====================================================================
// K5: sequential qLSTM scan (closed-form quantum layer).
// =====================================================================
__global__ void k_lstm(const float* __restrict__ Wf, const float* __restrict__ Wi,
                       const float* __restrict__ Wg_, const float* __restrict__ Wo2)
{
    const int lane = threadIdx.x & 31;
    const int warp = threadIdx.x >> 5;
    const int g = lane >> 3;
    const int b8 = lane & 7;
    const int b = warp * 8 + b8;
    const float* Wsel = (g == 0) ? Wf : (g == 1) ? Wi : (g == 2) ? Wg_ : Wo2;

    float Wh[4][4];
#pragma unroll
    for (int w = 0; w < 4; ++w)
#pragma unroll
        for (int j = 0; j < 4; ++j) Wh[w][j] = Wsel[w * 260 + 256 + j];

    const float hs = (g == 2) ? 1.f : 0.5f;
    const float as = (g == 2) ? 1.f : 0.5f;
    const float ab = (g == 2) ? 0.f : 0.5f;

    float cx0 = 0.f, cx1 = 0.f, cx2 = 0.f, cx3 = 0.f;
    float h0 = 0.f, h1 = 0.f, h2 = 0.f, h3 = 0.f;

    float4 a = *(const float4*)(g_A + ((size_t)0 * 16 + b) * 16 + g * 4);
    for (int t = 0; t < 512; ++t) {
        const int tn = (t + 1 < 512) ? (t + 1) : 511;
        float4 anext = *(const float4*)(g_A + ((size_t)tn * 16 + b) * 16 + g * 4);

        float an0 = a.x + Wh[0][0] * h0 + Wh[0][1] * h1 + Wh[0][2] * h2 + Wh[0][3] * h3;
        float an1 = a.y + Wh[1][0] * h0 + Wh[1][1] * h1 + Wh[1][2] * h2 + Wh[1][3] * h3;
        float an2 = a.z + Wh[2][0] * h0 + Wh[2][1] * h1 + Wh[2][2] * h2 + Wh[2][3] * h3;
        float an3 = a.w + Wh[3][0] * h0 + Wh[3][1] * h1 + Wh[3][2] * h2 + Wh[3][3] * h3;

        float c0 = __cosf(an0), c1 = __cosf(an1), c2 = __cosf(an2), c3 = __cosf(an3);
        float z1 = c0 * c1;
        float c12 = c1 * c2;
        float z0 = c12 * c3;
        float z2 = z1 * c2;
        float z3 = z2 * c3;

        float act0 = as * tanh_fast(hs * z0) + ab;
        float act1 = as * tanh_fast(hs * z1) + ab;
        float act2 = as * tanh_fast(hs * z2) + ab;
        float act3 = as * tanh_fast(hs * z3) + ab;

        const unsigned mask = 0xffffffffu;
        float f0 = __shfl_sync(mask, act0, b8),      f1 = __shfl_sync(mask, act1, b8);
        float f2 = __shfl_sync(mask, act2, b8),      f3 = __shfl_sync(mask, act3, b8);
        float i0 = __shfl_sync(mask, act0, 8 + b8),  i1 = __shfl_sync(mask, act1, 8 + b8);
        float i2 = __shfl_sync(mask, act2, 8 + b8),  i3 = __shfl_sync(mask, act3, 8 + b8);
        float gg0 = __shfl_sync(mask, act0, 16 + b8), gg1 = __shfl_sync(mask, act1, 16 + b8);
        float gg2 = __shfl_sync(mask, act2, 16 + b8), gg3 = __shfl_sync(mask, act3, 16 + b8);
        float o0 = __shfl_sync(mask, act0, 24 + b8), o1 = __shfl_sync(mask, act1, 24 + b8);
        float o2 = __shfl_sync(mask, act2, 24 + b8), o3 = __shfl_sync(mask, act3, 24 + b8);

        cx0 = f0 * cx0 + i0 * gg0;
        cx1 = f1 * cx1 + i1 * gg1;
        cx2 = f2 * cx2 + i2 * gg2;
        cx3 = f3 * cx3 + i3 * gg3;

        h0 = o0 * tanh_fast(cx0);
        h1 = o1 * tanh_fast(cx1);
        h2 = o2 * tanh_fast(cx2);
        h3 = o3 * tanh_fast(cx3);

        if (g == 0) *(float4*)(g_hs + ((size_t)t * 16 + b) * 4) = make_float4(h0, h1, h2, h3);
        a = anext;
    }
}

// =====================================================================
// K6: logits + log_softmax.
// =====================================================================
__global__ void k_logits(const float* __restrict__ Wt, const float* __restrict__ bt,
                         float* __restrict__ out)
{
    const int row = blockIdx.x * 8 + (threadIdx.x >> 5);
    const int lane = threadIdx.x & 31;
    const int b = row >> 9, t = row & 511;
    float4 h = *(const float4*)(g_hs + ((size_t)t * 16 + b) * 4);

    const int j0 = lane, j1 = lane + 32;
    float4 w0 = *(const float4*)(Wt + j0 * 4);
    float4 w1 = *(const float4*)(Wt + j1 * 4);
    float l0 = bt[j0] + h.x * w0.x + h.y * w0.y + h.z * w0.z + h.w * w0.w;
    float l1 = bt[j1] + h.x * w1.x + h.y * w1.y + h.z * w1.z + h.w * w1.w;

    float m = fmaxf(l0, l1);
#pragma unroll
    for (int o = 16; o >= 1; o >>= 1) m = fmaxf(m, __shfl_xor_sync(0xffffffffu, m, o));
    float s = __expf(l0 - m) + __expf(l1 - m);
#pragma unroll
    for (int o = 16; o >= 1; o >>= 1) s += __shfl_xor_sync(0xffffffffu, s, o);
    const float lse = m + logf(s);
    out[(size_t)row * 64 + j0] = l0 - lse;
    out[(size_t)row * 64 + j1] = l1 - lse;
}

// =====================================================================
extern "C" void kernel_launch(void* const* d_in, const int* in_sizes, int n_in,
                              void* d_out, int out_size)
{
    const int*   sent = (const int*)d_in[0];
    const float* emb  = (const float*)d_in[1];
    const float* Wq = (const float*)d_in[2];  const float* bq = (const float*)d_in[3];
    const float* Wk = (const float*)d_in[4];  const float* bk = (const float*)d_in[5];
    const float* Wv = (const float*)d_in[6];  const float* bv = (const float*)d_in[7];
    const float* Wo = (const float*)d_in[8];  const float* bo = (const float*)d_in[9];
    const float* Wf = (const float*)d_in[10]; const float* bf = (const float*)d_in[11]; const float* thf = (const float*)d_in[12];
    const float* Wi = (const float*)d_in[13]; const float* bi = (const float*)d_in[14]; const float* thi = (const float*)d_in[15];
    const float* Wg = (const float*)d_in[16]; const float* bg = (const float*)d_in[17]; const float* thg = (const float*)d_in[18];
    const float* Wo2= (const float*)d_in[19]; const float* bo2= (const float*)d_in[20]; const float* tho = (const float*)d_in[21];
    const float* Wt = (const float*)d_in[22]; const float* bt = (const float*)d_in[23];
    float* out = (float*)d_out;

    const int flash_smem = (2 * 64 * FS + 64 * 64) * 4;   // 51200 B
    cudaFuncSetAttribute(k_flash, cudaFuncAttributeMaxDynamicSharedMemorySize, flash_smem);

    k_prepA<<<4096, 256>>>(sent, emb);
    k_prepB<<<384, 256>>>(Wq, Wk, Wv);
    k_qkv_mma<<<dim3(64, 6), 256>>>(bq, bk, bv);
    k_combine<<<16, 256>>>(Wf, bf, thf, Wi, bi, thi, Wg, bg, thg, Wo2, bo2, tho, Wo, bo);
    k_flash<<<dim3(8, 64), 256, flash_smem>>>();
    k_gates<<<512, 256>>>();
    k_lstm<<<1, 64>>>(Wf, Wi, Wg, Wo2);
    k_logits<<<1024, 256>>>(Wt, bt, out);
}

// round 17
// speedup vs baseline: 1.8454x; 1.8454x over previous
#include <cuda_runtime.h>
#include <cuda_bf16.h>

// ---------------- device scratch (no allocs allowed) ----------------
__device__ float g_o[8192*256];   // attention output (pre-Wo), merged heads
__device__ float g_Wc[16*256];    // combined gate weights
__device__ float g_bc[16];        // combined gate bias (+theta)
__device__ float g_A[512*16*16];  // (t, b, gate*4+w) precomputed angles
__device__ float g_hs[512*16*4];  // lstm hidden states (t, b, w)
// split-precision bf16 QKV-GEMM operands, row-major:
__device__ __align__(16) unsigned short g_Abf[8192*768];  // [Ahi|Alo|Ahi]
__device__ __align__(16) unsigned short g_Bbf[768*768];   // [Whi|Whi|Wlo]
// q/k/v results as bf16 hi/lo pairs (flash consumes these):
__device__ __align__(16) unsigned short g_qh[8192*256];
__device__ __align__(16) unsigned short g_ql[8192*256];
__device__ __align__(16) unsigned short g_kh[8192*256];
__device__ __align__(16) unsigned short g_kl[8192*256];
__device__ __align__(16) unsigned short g_vh[8192*256];
__device__ __align__(16) unsigned short g_vl[8192*256];

__device__ __forceinline__ float tanh_fast(float x) {
    float y; asm("tanh.approx.f32 %0, %1;" : "=f"(y) : "f"(x)); return y;
}
__device__ __forceinline__ unsigned smem_u32(const void* p) {
    unsigned a; asm("{ .reg .u64 t; cvta.to.shared.u64 t, %1; cvt.u32.u64 %0, t; }" : "=r"(a) : "l"(p));
    return a;
}
__device__ __forceinline__ void ldm4(unsigned& r0, unsigned& r1, unsigned& r2, unsigned& r3, unsigned addr) {
    asm volatile("ldmatrix.sync.aligned.m8n8.x4.shared.b16 {%0,%1,%2,%3}, [%4];"
                 : "=r"(r0), "=r"(r1), "=r"(r2), "=r"(r3) : "r"(addr));
}
__device__ __forceinline__ void ldm4t(unsigned& r0, unsigned& r1, unsigned& r2, unsigned& r3, unsigned addr) {
    asm volatile("ldmatrix.sync.aligned.m8n8.x4.trans.shared.b16 {%0,%1,%2,%3}, [%4];"
                 : "=r"(r0), "=r"(r1), "=r"(r2), "=r"(r3) : "r"(addr));
}
__device__ __forceinline__ void mma16816(float* c, const unsigned* a, const unsigned* b) {
    asm volatile("mma.sync.aligned.m16n8k16.row.col.f32.bf16.bf16.f32 "
                 "{%0,%1,%2,%3}, {%4,%5,%6,%7}, {%8,%9}, {%0,%1,%2,%3};"
                 : "+f"(c[0]), "+f"(c[1]), "+f"(c[2]), "+f"(c[3])
                 : "r"(a[0]), "r"(a[1]), "r"(a[2]), "r"(a[3]), "r"(b[0]), "r"(b[1]));
}
// pack two fp32 into bf16x2 (lo -> low half, hi -> high half)
__device__ __forceinline__ unsigned pack_bf16(float lo, float hi) {
    unsigned d; asm("cvt.rn.bf16x2.f32 %0, %1, %2;" : "=r"(d) : "f"(hi), "f"(lo)); return d;
}
__device__ __forceinline__ float bfu_lo(unsigned u) { return __uint_as_float(u << 16); }
__device__ __forceinline__ float bfu_hi(unsigned u) { return __uint_as_float(u & 0xFFFF0000u); }

#define VS 72   // bf16 smem row stride (144B: 16B-aligned, conflict-free ldmatrix)

// =====================================================================
// P1: gather emb rows, split fp32 -> bf16 hi/lo, write row-major A'.
// =====================================================================
__global__ void k_prepA(const int* __restrict__ sent, const float* __restrict__ emb)
{
    const int idx = blockIdx.x * 256 + threadIdx.x;   // 8192*128
    const int r = idx >> 7, c = (idx & 127) * 2;
    const float2 x = *(const float2*)(emb + (size_t)sent[r] * 256 + c);
    const unsigned hp = pack_bf16(__bfloat162float(__float2bfloat16(x.x)) * 0.f + 0.f, 0.f) * 0u; // (unused dummy removed below)
    const __nv_bfloat16 h0 = __float2bfloat16(x.x), h1 = __float2bfloat16(x.y);
    const __nv_bfloat16 l0 = __float2bfloat16(x.x - __bfloat162float(h0));
    const __nv_bfloat16 l1 = __float2bfloat16(x.y - __bfloat162float(h1));
    const unsigned hpack = (unsigned)__bfloat16_as_ushort(h0) | ((unsigned)__bfloat16_as_ushort(h1) << 16);
    const unsigned lpack = (unsigned)__bfloat16_as_ushort(l0) | ((unsigned)__bfloat16_as_ushort(l1) << 16);
    unsigned short* dst = g_Abf + (size_t)r * 768;
    *(unsigned*)(dst + c)       = hpack;
    *(unsigned*)(dst + 256 + c) = lpack;
    *(unsigned*)(dst + 512 + c) = hpack;
    (void)hp;
}

// =====================================================================
// P2: same for stacked weights [Wq;Wk;Wv] (768 x 256) -> B'.
// =====================================================================
__global__ void k_prepB(const float* __restrict__ Wq, const float* __restrict__ Wk,
                        const float* __restrict__ Wv)
{
    const int idx = blockIdx.x * 256 + threadIdx.x;   // 768*128
    const int n = idx >> 7, c = (idx & 127) * 2;
    const int which = n >> 8, wn = n & 255;
    const float* W = (which == 0) ? Wq : (which == 1) ? Wk : Wv;
    const float2 x = *(const float2*)(W + (size_t)wn * 256 + c);
    const __nv_bfloat16 h0 = __float2bfloat16(x.x), h1 = __float2bfloat16(x.y);
    const __nv_bfloat16 l0 = __float2bfloat16(x.x - __bfloat162float(h0));
    const __nv_bfloat16 l1 = __float2bfloat16(x.y - __bfloat162float(h1));
    const unsigned hpack = (unsigned)__bfloat16_as_ushort(h0) | ((unsigned)__bfloat16_as_ushort(h1) << 16);
    const unsigned lpack = (unsigned)__bfloat16_as_ushort(l0) | ((unsigned)__bfloat16_as_ushort(l1) << 16);
    unsigned short* dst = g_Bbf + (size_t)n * 768;
    *(unsigned*)(dst + c)       = hpack;
    *(unsigned*)(dst + 256 + c) = hpack;
    *(unsigned*)(dst + 512 + c) = lpack;
}

// =====================================================================
// K1: QKV GEMM on tensor cores (m16n8k16 bf16, f32 acc).
// grid (64 mt, 6 nt), 256 thr = 8 warps (4m x 2n), warp tile 32x64.
// Epilogue writes q/k/v directly as bf16 hi/lo pairs.
// =====================================================================
__global__ void __launch_bounds__(256, 2) k_qkv_mma(
    const float* __restrict__ bq, const float* __restrict__ bk, const float* __restrict__ bv)
{
    __shared__ __align__(16) unsigned short As[128][72];
    __shared__ __align__(16) unsigned short Bs[128][72];
    const int tid = threadIdx.x;
    const int warp = tid >> 5, lane = tid & 31;
    const int wm = warp >> 1, wn = warp & 1;
    const int mt = blockIdx.x, nt = blockIdx.y;

    float c[2][8][4] = {};

    for (int kc = 0; kc < 12; ++kc) {
#pragma unroll
        for (int i = 0; i < 4; ++i) {
            const int e = tid + i * 256;
            const int row = e >> 3, c16 = e & 7;
            *(uint4*)&As[row][c16 * 8] =
                *(const uint4*)(g_Abf + (size_t)(mt * 128 + row) * 768 + kc * 64 + c16 * 8);
            *(uint4*)&Bs[row][c16 * 8] =
                *(const uint4*)(g_Bbf + (size_t)(nt * 128 + row) * 768 + kc * 64 + c16 * 8);
        }
        __syncthreads();

#pragma unroll
        for (int ks = 0; ks < 4; ++ks) {
            unsigned a[2][4];
#pragma unroll
            for (int mi = 0; mi < 2; ++mi) {
                const unsigned addr = smem_u32(&As[wm * 32 + mi * 16 + (lane & 15)][ks * 16 + (lane >> 4) * 8]);
                ldm4(a[mi][0], a[mi][1], a[mi][2], a[mi][3], addr);
            }
            unsigned b[8][2];
#pragma unroll
            for (int nb4 = 0; nb4 < 4; ++nb4) {
                unsigned r0, r1, r2, r3;
                const unsigned addr = smem_u32(&Bs[wn * 64 + nb4 * 16 + (lane & 15)][ks * 16 + (lane >> 4) * 8]);
                ldm4(r0, r1, r2, r3, addr);
                b[nb4 * 2][0] = r0; b[nb4 * 2 + 1][0] = r1;
                b[nb4 * 2][1] = r2; b[nb4 * 2 + 1][1] = r3;
            }
#pragma unroll
            for (int mi = 0; mi < 2; ++mi)
#pragma unroll
                for (int nb = 0; nb < 8; ++nb)
                    mma16816(c[mi][nb], a[mi], b[nb]);
        }
        __syncthreads();
    }

    // epilogue: bias + q-scale, split fp32 -> bf16 hi/lo, packed stores
    const int ncol0 = nt << 7;
    const int which = ncol0 >> 8, wn0 = ncol0 & 255;
    const float* bias = (which == 0) ? bq : (which == 1) ? bk : bv;
    const float qs = (which == 0) ? 0.125f : 1.0f;
    unsigned short* dsth = (which == 0) ? g_qh : (which == 1) ? g_kh : g_vh;
    unsigned short* dstl = (which == 0) ? g_ql : (which == 1) ? g_kl : g_vl;
#pragma unroll
    for (int mi = 0; mi < 2; ++mi) {
        const int row = mt * 128 + wm * 32 + mi * 16 + (lane >> 2);
#pragma unroll
        for (int nb = 0; nb < 8; ++nb) {
            const int colg = wn0 + wn * 64 + nb * 8 + (lane & 3) * 2;
            const float b0 = bias[colg], b1 = bias[colg + 1];
            {
                const float v0 = (c[mi][nb][0] + b0) * qs, v1 = (c[mi][nb][1] + b1) * qs;
                const unsigned ph = pack_bf16(v0, v1);
                const unsigned pl = pack_bf16(v0 - bfu_lo(ph), v1 - bfu_hi(ph));
                *(unsigned*)(dsth + (size_t)row * 256 + colg) = ph;
                *(unsigned*)(dstl + (size_t)row * 256 + colg) = pl;
            }
            {
                const float v0 = (c[mi][nb][2] + b0) * qs, v1 = (c[mi][nb][3] + b1) * qs;
                const unsigned ph = pack_bf16(v0, v1);
                const unsigned pl = pack_bf16(v0 - bfu_lo(ph), v1 - bfu_hi(ph));
                *(unsigned*)(dsth + (size_t)(row + 8) * 256 + colg) = ph;
                *(unsigned*)(dstl + (size_t)(row + 8) * 256 + colg) = pl;
            }
        }
    }
}

// =====================================================================
// K2: flash attention on tensor cores, no-max softmax, split-bf16.
// grid (8, 64), 128 thr = 4 warps; warp owns 16 q-rows; tile 64 k.
// smem: Qh Ql Kh Kl Vh Vl, each [64][VS] bf16.
// S = Qh Kh^T + Ql Kh^T + Qh Kl^T ; P = exp(S) split hi/lo;
// O += Ph Vh + Pl Vh + Ph Vl  (V frags via ldmatrix.trans).
// =====================================================================
__global__ void __launch_bounds__(128, 3) k_flash_mma()
{
    extern __shared__ __align__(16) unsigned short smu[];
    unsigned short* Qh = smu;
    unsigned short* Ql = smu + 4608;
    unsigned short* Kh = smu + 2 * 4608;
    unsigned short* Kl = smu + 3 * 4608;
    unsigned short* Vh = smu + 4 * 4608;
    unsigned short* Vl = smu + 5 * 4608;

    const int bh = blockIdx.y;
    const int bidx = bh >> 2, h = bh & 3;
    const int m0 = blockIdx.x * 64;
    const int tid = threadIdx.x;
    const int warp = tid >> 5, lane = tid & 31;

    // load Q tile (64 x 64) hi/lo
#pragma unroll
    for (int j = 0; j < 4; ++j) {
        const int chunk = tid + j * 128;
        const int row = chunk >> 3, c8 = (chunk & 7) * 8;
        const size_t g = (size_t)(bidx * 512 + m0 + row) * 256 + h * 64 + c8;
        *(uint4*)&Qh[row * VS + c8] = *(const uint4*)(g_qh + g);
        *(uint4*)&Ql[row * VS + c8] = *(const uint4*)(g_ql + g);
    }

    float o[8][4] = {};
    float lp0 = 0.f, lp1 = 0.f;

    for (int kk0 = 0; kk0 < 512; kk0 += 64) {
#pragma unroll
        for (int j = 0; j < 4; ++j) {
            const int chunk = tid + j * 128;
            const int row = chunk >> 3, c8 = (chunk & 7) * 8;
            const size_t g = (size_t)(bidx * 512 + kk0 + row) * 256 + h * 64 + c8;
            *(uint4*)&Kh[row * VS + c8] = *(const uint4*)(g_kh + g);
            *(uint4*)&Kl[row * VS + c8] = *(const uint4*)(g_kl + g);
            *(uint4*)&Vh[row * VS + c8] = *(const uint4*)(g_vh + g);
            *(uint4*)&Vl[row * VS + c8] = *(const uint4*)(g_vl + g);
        }
        __syncthreads();

        // ---- S = Q K^T (3-term split) ----
        float c[8][4] = {};
#pragma unroll
        for (int ks = 0; ks < 4; ++ks) {
            const int acol = ks * 16 + (lane >> 4) * 8;
            unsigned aH[4], aL[4], bb[8][2];
            ldm4(aH[0], aH[1], aH[2], aH[3], smem_u32(&Qh[(warp * 16 + (lane & 15)) * VS + acol]));
            ldm4(aL[0], aL[1], aL[2], aL[3], smem_u32(&Ql[(warp * 16 + (lane & 15)) * VS + acol]));
#pragma unroll
            for (int nb2 = 0; nb2 < 4; ++nb2) {
                unsigned r0, r1, r2, r3;
                ldm4(r0, r1, r2, r3, smem_u32(&Kh[(nb2 * 16 + (lane & 15)) * VS + acol]));
                bb[nb2 * 2][0] = r0; bb[nb2 * 2 + 1][0] = r1;
                bb[nb2 * 2][1] = r2; bb[nb2 * 2 + 1][1] = r3;
            }
#pragma unroll
            for (int nb = 0; nb < 8; ++nb) { mma16816(c[nb], aH, bb[nb]); mma16816(c[nb], aL, bb[nb]); }
#pragma unroll
            for (int nb2 = 0; nb2 < 4; ++nb2) {
                unsigned r0, r1, r2, r3;
                ldm4(r0, r1, r2, r3, smem_u32(&Kl[(nb2 * 16 + (lane & 15)) * VS + acol]));
                bb[nb2 * 2][0] = r0; bb[nb2 * 2 + 1][0] = r1;
                bb[nb2 * 2][1] = r2; bb[nb2 * 2 + 1][1] = r3;
            }
#pragma unroll
            for (int nb = 0; nb < 8; ++nb) mma16816(c[nb], aH, bb[nb]);
        }

        // ---- exp (no max; scores provably tiny) + row partial sums ----
#pragma unroll
        for (int nb = 0; nb < 8; ++nb) {
            c[nb][0] = __expf(c[nb][0]); c[nb][1] = __expf(c[nb][1]);
            c[nb][2] = __expf(c[nb][2]); c[nb][3] = __expf(c[nb][3]);
            lp0 += c[nb][0] + c[nb][1];
            lp1 += c[nb][2] + c[nb][3];
        }

        // ---- O += P V (repack C-frags to A-frags, V via ldmatrix.trans) ----
#pragma unroll
        for (int ks = 0; ks < 4; ++ks) {
            const float* t0 = c[2 * ks];
            const float* t1 = c[2 * ks + 1];
            unsigned aPh[4], aPl[4];
            aPh[0] = pack_bf16(t0[0], t0[1]);
            aPh[1] = pack_bf16(t0[2], t0[3]);
            aPh[2] = pack_bf16(t1[0], t1[1]);
            aPh[3] = pack_bf16(t1[2], t1[3]);
            aPl[0] = pack_bf16(t0[0] - bfu_lo(aPh[0]), t0[1] - bfu_hi(aPh[0]));
            aPl[1] = pack_bf16(t0[2] - bfu_lo(aPh[1]), t0[3] - bfu_hi(aPh[1]));
            aPl[2] = pack_bf16(t1[0] - bfu_lo(aPh[2]), t1[1] - bfu_hi(aPh[2]));
            aPl[3] = pack_bf16(t1[2] - bfu_lo(aPh[3]), t1[3] - bfu_hi(aPh[3]));

            const int vrow = ks * 16 + (lane & 7) + ((lane >> 4) & 1) * 8;
            const int vcol8 = ((lane >> 3) & 1) * 8;
#pragma unroll
            for (int nb2 = 0; nb2 < 4; ++nb2) {
                unsigned r0, r1, r2, r3;
                unsigned bv0[2], bv1[2];
                ldm4t(r0, r1, r2, r3, smem_u32(&Vh[vrow * VS + nb2 * 16 + vcol8]));
                bv0[0] = r0; bv1[0] = r1; bv0[1] = r2; bv1[1] = r3;
                mma16816(o[2 * nb2],     aPh, bv0);
                mma16816(o[2 * nb2 + 1], aPh, bv1);
                mma16816(o[2 * nb2],     aPl, bv0);
                mma16816(o[2 * nb2 + 1], aPl, bv1);
                ldm4t(r0, r1, r2, r3, smem_u32(&Vl[vrow * VS + nb2 * 16 + vcol8]));
                bv0[0] = r0; bv1[0] = r1; bv0[1] = r2; bv1[1] = r3;
                mma16816(o[2 * nb2],     aPh, bv0);
                mma16816(o[2 * nb2 + 1], aPh, bv1);
            }
        }
        __syncthreads();   // protect K/V smem before next tile's loads
    }

    // final row-sum reduction across the 4 lanes sharing a row
    lp0 += __shfl_xor_sync(0xffffffffu, lp0, 1);
    lp0 += __shfl_xor_sync(0xffffffffu, lp0, 2);
    lp1 += __shfl_xor_sync(0xffffffffu, lp1, 1);
    lp1 += __shfl_xor_sync(0xffffffffu, lp1, 2);
    const float inv0 = __fdividef(1.f, lp0);
    const float inv1 = __fdividef(1.f, lp1);

    const int row0 = bidx * 512 + m0 + warp * 16 + (lane >> 2);
#pragma unroll
    for (int nb = 0; nb < 8; ++nb) {
        const int col = h * 64 + nb * 8 + (lane & 3) * 2;
        *(float2*)(g_o + (size_t)row0 * 256 + col)       = make_float2(o[nb][0] * inv0, o[nb][1] * inv0);
        *(float2*)(g_o + (size_t)(row0 + 8) * 256 + col) = make_float2(o[nb][2] * inv1, o[nb][3] * inv1);
    }
}

// =====================================================================
// K3: fold Wo into gate projections — parallel (16 blocks) + ILP.
// =====================================================================
__global__ void k_combine(const float* __restrict__ Wf, const float* __restrict__ bf, const float* __restrict__ thf,
                          const float* __restrict__ Wi, const float* __restrict__ bi, const float* __restrict__ thi,
                          const float* __restrict__ Wg_, const float* __restrict__ bg, const float* __restrict__ thg,
                          const float* __restrict__ Wo2, const float* __restrict__ bo2, const float* __restrict__ tho,
                          const float* __restrict__ Wo, const float* __restrict__ bo)
{
    const int n = blockIdx.x;            // 0..15
    const int g = n >> 2, w = n & 3;
    const float* Wsel = (g == 0) ? Wf : (g == 1) ? Wi : (g == 2) ? Wg_ : Wo2;
    __shared__ float sw[256];
    __shared__ float red[256];
    const int c = threadIdx.x;
    sw[c] = Wsel[w * 260 + c];
    __syncthreads();

    float a0 = 0.f, a1 = 0.f, a2 = 0.f, a3 = 0.f;
#pragma unroll 8
    for (int d = 0; d < 256; d += 4) {
        a0 += sw[d + 0] * Wo[(d + 0) * 256 + c];
        a1 += sw[d + 1] * Wo[(d + 1) * 256 + c];
        a2 += sw[d + 2] * Wo[(d + 2) * 256 + c];
        a3 += sw[d + 3] * Wo[(d + 3) * 256 + c];
    }
    g_Wc[n * 256 + c] = (a0 + a1) + (a2 + a3);

    red[c] = sw[c] * bo[c];
    __syncthreads();
#pragma unroll
    for (int s = 128; s > 0; s >>= 1) {
        if (c < s) red[c] += red[c + s];
        __syncthreads();
    }
    if (c == 0) {
        const float bb = (g == 0) ? bf[w] : (g == 1) ? bi[w] : (g == 2) ? bg[w] : bo2[w];
        const float tt = (g == 0) ? thf[w] : (g == 1) ? thi[w] : (g == 2) ? thg[w] : tho[w];
        g_bc[n] = red[0] + bb + tt;
    }
}

// =====================================================================
// K4: gate angle precompute, rows staged through smem.
// =====================================================================
__global__ void k_gates()
{
    __shared__ float sW[256][16];
    __shared__ float sb[16];
    __shared__ __align__(16) float sX[16 * 256];
    const int tid = threadIdx.x;
    for (int e = tid; e < 4096; e += 256) {
        const int k = e >> 4, n = e & 15;
        sW[k][n] = g_Wc[n * 256 + k];
    }
    if (tid < 16) sb[tid] = g_bc[tid];
    const int r0 = blockIdx.x * 16;
    const float4* src = (const float4*)(g_o + (size_t)r0 * 256);
    float4* dst = (float4*)sX;
    for (int i = tid; i < 1024; i += 256) dst[i] = src[i];
    __syncthreads();

    const int n = tid & 15, lr = tid >> 4;
    const float* x = sX + lr * 256;
    float acc = 0.f;
#pragma unroll 8
    for (int k = 0; k < 256; k += 4) {
        float4 a4 = *(const float4*)(x + k);
        acc += a4.x * sW[k + 0][n] + a4.y * sW[k + 1][n] + a4.z * sW[k + 2][n] + a4.w * sW[k + 3][n];
    }
    const int r = r0 + lr, b = r >> 9, t = r & 511;
    g_A[(t * 16 + b) * 16 + n] = acc + sb[n];
}

// =====================================================================
// K5: sequential qLSTM scan (closed-form quantum layer).
// =====================================================================
__global__ void k_lstm(const float* __restrict__ Wf, const float* __restrict__ Wi,
                       const float* __restrict__ Wg_, const float* __restrict__ Wo2)
{
    const int lane = threadIdx.x & 31;
    const int warp = threadIdx.x >> 5;
    const int g = lane >> 3;
    const int b8 = lane & 7;
    const int b = warp * 8 + b8;
    const float* Wsel = (g == 0) ? Wf : (g == 1) ? Wi : (g == 2) ? Wg_ : Wo2;

    float Wh[4][4];
#pragma unroll
    for (int w = 0; w < 4; ++w)
#pragma unroll
        for (int j = 0; j < 4; ++j) Wh[w][j] = Wsel[w * 260 + 256 + j];

    const float hs = (g == 2) ? 1.f : 0.5f;
    const float as = (g == 2) ? 1.f : 0.5f;
    const float ab = (g == 2) ? 0.f : 0.5f;

    float cx0 = 0.f, cx1 = 0.f, cx2 = 0.f, cx3 = 0.f;
    float h0 = 0.f, h1 = 0.f, h2 = 0.f, h3 = 0.f;

    float4 a = *(const float4*)(g_A + ((size_t)0 * 16 + b) * 16 + g * 4);
    for (int t = 0; t < 512; ++t) {
        const int tn = (t + 1 < 512) ? (t + 1) : 511;
        float4 anext = *(const float4*)(g_A + ((size_t)tn * 16 + b) * 16 + g * 4);

        float an0 = a.x + Wh[0][0] * h0 + Wh[0][1] * h1 + Wh[0][2] * h2 + Wh[0][3] * h3;
        float an1 = a.y + Wh[1][0] * h0 + Wh[1][1] * h1 + Wh[1][2] * h2 + Wh[1][3] * h3;
        float an2 = a.z + Wh[2][0] * h0 + Wh[2][1] * h1 + Wh[2][2] * h2 + Wh[2][3] * h3;
        float an3 = a.w + Wh[3][0] * h0 + Wh[3][1] * h1 + Wh[3][2] * h2 + Wh[3][3] * h3;

        float c0 = __cosf(an0), c1 = __cosf(an1), c2 = __cosf(an2), c3 = __cosf(an3);
        float z1 = c0 * c1;
        float c12 = c1 * c2;
        float z0 = c12 * c3;
        float z2 = z1 * c2;
        float z3 = z2 * c3;

        float act0 = as * tanh_fast(hs * z0) + ab;
        float act1 = as * tanh_fast(hs * z1) + ab;
        float act2 = as * tanh_fast(hs * z2) + ab;
        float act3 = as * tanh_fast(hs * z3) + ab;

        const unsigned mask = 0xffffffffu;
        float f0 = __shfl_sync(mask, act0, b8),      f1 = __shfl_sync(mask, act1, b8);
        float f2 = __shfl_sync(mask, act2, b8),      f3 = __shfl_sync(mask, act3, b8);
        float i0 = __shfl_sync(mask, act0, 8 + b8),  i1 = __shfl_sync(mask, act1, 8 + b8);
        float i2 = __shfl_sync(mask, act2, 8 + b8),  i3 = __shfl_sync(mask, act3, 8 + b8);
        float gg0 = __shfl_sync(mask, act0, 16 + b8), gg1 = __shfl_sync(mask, act1, 16 + b8);
        float gg2 = __shfl_sync(mask, act2, 16 + b8), gg3 = __shfl_sync(mask, act3, 16 + b8);
        float o0 = __shfl_sync(mask, act0, 24 + b8), o1 = __shfl_sync(mask, act1, 24 + b8);
        float o2 = __shfl_sync(mask, act2, 24 + b8), o3 = __shfl_sync(mask, act3, 24 + b8);

        cx0 = f0 * cx0 + i0 * gg0;
        cx1 = f1 * cx1 + i1 * gg1;
        cx2 = f2 * cx2 + i2 * gg2;
        cx3 = f3 * cx3 + i3 * gg3;

        h0 = o0 * tanh_fast(cx0);
        h1 = o1 * tanh_fast(cx1);
        h2 = o2 * tanh_fast(cx2);
        h3 = o3 * tanh_fast(cx3);

        if (g == 0) *(float4*)(g_hs + ((size_t)t * 16 + b) * 4) = make_float4(h0, h1, h2, h3);
        a = anext;
    }
}

// =====================================================================
// K6: logits + log_softmax.
// =====================================================================
__global__ void k_logits(const float* __restrict__ Wt, const float* __restrict__ bt,
                         float* __restrict__ out)
{
    const int row = blockIdx.x * 8 + (threadIdx.x >> 5);
    const int lane = threadIdx.x & 31;
    const int b = row >> 9, t = row & 511;
    float4 h = *(const float4*)(g_hs + ((size_t)t * 16 + b) * 4);

    const int j0 = lane, j1 = lane + 32;
    float4 w0 = *(const float4*)(Wt + j0 * 4);
    float4 w1 = *(const float4*)(Wt + j1 * 4);
    float l0 = bt[j0] + h.x * w0.x + h.y * w0.y + h.z * w0.z + h.w * w0.w;
    float l1 = bt[j1] + h.x * w1.x + h.y * w1.y + h.z * w1.z + h.w * w1.w;

    float m = fmaxf(l0, l1);
#pragma unroll
    for (int o = 16; o >= 1; o >>= 1) m = fmaxf(m, __shfl_xor_sync(0xffffffffu, m, o));
    float s = __expf(l0 - m) + __expf(l1 - m);
#pragma unroll
    for (int o = 16; o >= 1; o >>= 1) s += __shfl_xor_sync(0xffffffffu, s, o);
    const float lse = m + logf(s);
    out[(size_t)row * 64 + j0] = l0 - lse;
    out[(size_t)row * 64 + j1] = l1 - lse;
}

// =====================================================================
extern "C" void kernel_launch(void* const* d_in, const int* in_sizes, int n_in,
                              void* d_out, int out_size)
{
    const int*   sent = (const int*)d_in[0];
    const float* emb  = (const float*)d_in[1];
    const float* Wq = (const float*)d_in[2];  const float* bq = (const float*)d_in[3];
    const float* Wk = (const float*)d_in[4];  const float* bk = (const float*)d_in[5];
    const float* Wv = (const float*)d_in[6];  const float* bv = (const float*)d_in[7];
    const float* Wo = (const float*)d_in[8];  const float* bo = (const float*)d_in[9];
    const float* Wf = (const float*)d_in[10]; const float* bf = (const float*)d_in[11]; const float* thf = (const float*)d_in[12];
    const float* Wi = (const float*)d_in[13]; const float* bi = (const float*)d_in[14]; const float* thi = (const float*)d_in[15];
    const float* Wg = (const float*)d_in[16]; const float* bg = (const float*)d_in[17]; const float* thg = (const float*)d_in[18];
    const float* Wo2= (const float*)d_in[19]; const float* bo2= (const float*)d_in[20]; const float* tho = (const float*)d_in[21];
    const float* Wt = (const float*)d_in[22]; const float* bt = (const float*)d_in[23];
    float* out = (float*)d_out;

    const int flash_smem = 6 * 4608 * 2;   // 55296 B
    cudaFuncSetAttribute(k_flash_mma, cudaFuncAttributeMaxDynamicSharedMemorySize, flash_smem);

    k_prepA<<<4096, 256>>>(sent, emb);
    k_prepB<<<384, 256>>>(Wq, Wk, Wv);
    k_qkv_mma<<<dim3(64, 6), 256>>>(bq, bk, bv);
    k_combine<<<16, 256>>>(Wf, bf, thf, Wi, bi, thi, Wg, bg, thg, Wo2, bo2, tho, Wo, bo);
    k_flash_mma<<<dim3(8, 64), 128, flash_smem>>>();
    k_gates<<<512, 256>>>();
    k_lstm<<<1, 64>>>(Wf, Wi, Wg, Wo2);
    k_logits<<<1024, 256>>>(Wt, bt, out);
}